// round 1
// baseline (speedup 1.0000x reference)
#include <cuda_runtime.h>
#include <math.h>

#define Bq 2
#define Lq 2048
#define Sq 2048
#define Hq 8
#define Eq 64
#define TL 16          // l rows per block
#define TS 256         // s chunk
#define NTHR 256
#define SCALE 0.125f   // 1/sqrt(64)
#define EPSF 1e-8f

struct Smem {
    float sS[TL][Sq];       // scores -> att (131072 B)
    float sK[TS][Eq + 1];   // K or V chunk, stride 65 (66560 B)
    float sQ[TL][Eq];       // Q tile / V-phase reduction buffer (4096 B)
    float sKm[Sq];          // 0 or -inf per key pos (8192 B)
    int   sPos[Sq];         // pos per key index (8192 B)
    int   sPl[TL];
    int   sQm[TL];
};

__global__ __launch_bounds__(NTHR, 1)
void attn_kernel(const float* __restrict__ Q, const float* __restrict__ K,
                 const float* __restrict__ V,
                 const int* __restrict__ mk, const int* __restrict__ mq,
                 const int* __restrict__ pos, const int* __restrict__ cmaskp,
                 float* __restrict__ outV, float* __restrict__ outA,
                 float* __restrict__ outE)
{
    extern __shared__ char smem_raw[];
    Smem& sm = *reinterpret_cast<Smem*>(smem_raw);
    const int t = threadIdx.x;
    const int TILES = Lq / TL;
    const int lt = blockIdx.x % TILES;
    const int h  = (blockIdx.x / TILES) % Hq;
    const int b  = blockIdx.x / (TILES * Hq);
    const int l0 = lt * TL;
    const int causal = cmaskp[0];

    // ---- preload masks / pos ----
    for (int s = t; s < Sq; s += NTHR) {
        sm.sKm[s]  = mk[b * Sq + s] ? -INFINITY : 0.0f;
        sm.sPos[s] = pos[b * Lq + s];
    }
    if (t < TL) {
        sm.sPl[t] = pos[b * Lq + l0 + t];
        sm.sQm[t] = mq[b * Lq + l0 + t];
    }
    // ---- load Q tile (16 rows x 64) ----
    {
        int r = t >> 4, v = t & 15;   // 256 threads -> 16x16 float4
        const float4 qv = *reinterpret_cast<const float4*>(
            Q + (((size_t)b * Lq + l0 + r) * Hq + h) * Eq + 4 * v);
        *reinterpret_cast<float4*>(&sm.sQ[r][4 * v]) = qv;
    }

    const int lmax = l0 + TL - 1;
    const int nch  = causal ? (lmax / TS + 1) : (Sq / TS);
    const int ncs  = nch * TS;

    // ================= Phase 1: scores =================
    const int tc = t & 31, rg = t >> 5;   // rows {rg, rg+8}, cols {tc+32j}
    for (int ch = 0; ch < nch; ch++) {
        const int c0 = ch * TS;
        __syncthreads();
        // load K chunk (coalesced), SMEM stride 65
        for (int p = t; p < TS * 16; p += NTHR) {
            int s = p >> 4, v = p & 15;
            const float4 kv = *reinterpret_cast<const float4*>(
                K + (((size_t)b * Sq + c0 + s) * Hq + h) * Eq + 4 * v);
            float* dst = &sm.sK[s][4 * v];
            dst[0] = kv.x; dst[1] = kv.y; dst[2] = kv.z; dst[3] = kv.w;
        }
        __syncthreads();

        float acc0[8], acc1[8];
        #pragma unroll
        for (int j = 0; j < 8; j++) { acc0[j] = 0.f; acc1[j] = 0.f; }
        #pragma unroll 4
        for (int e = 0; e < Eq; e++) {
            const float q0 = sm.sQ[rg][e];
            const float q1 = sm.sQ[rg + 8][e];
            #pragma unroll
            for (int j = 0; j < 8; j++) {
                const float kk = sm.sK[tc + 32 * j][e];
                acc0[j] += q0 * kk;
                acc1[j] += q1 * kk;
            }
        }
        const int pl0 = sm.sPl[rg], pl1 = sm.sPl[rg + 8];
        #pragma unroll
        for (int j = 0; j < 8; j++) {
            const int s = c0 + tc + 32 * j;
            const float addm = sm.sKm[s];
            const int ps = sm.sPos[s];
            float v0 = acc0[j] * SCALE + addm;
            float v1 = acc1[j] * SCALE + addm;
            if (causal && ps > pl0) v0 = -INFINITY;
            if (causal && ps > pl1) v1 = -INFINITY;
            sm.sS[rg][s]     = v0;
            sm.sS[rg + 8][s] = v1;
        }
    }
    __syncthreads();

    // ================= Phase 2: softmax + entropy =================
    {
        const int r = t >> 4, q = t & 15;   // 16 threads per row
        const int qm = sm.sQm[r];
        float m = -INFINITY;
        for (int s = q; s < ncs; s += 16) m = fmaxf(m, sm.sS[r][s]);
        #pragma unroll
        for (int k = 8; k >= 1; k >>= 1)
            m = fmaxf(m, __shfl_xor_sync(0xffffffffu, m, k));
        float sum = 0.f;
        if (m != -INFINITY)
            for (int s = q; s < ncs; s += 16) sum += __expf(sm.sS[r][s] - m);
        #pragma unroll
        for (int k = 8; k >= 1; k >>= 1)
            sum += __shfl_xor_sync(0xffffffffu, sum, k);
        const float inv = (m == -INFINITY) ? 0.0f : 1.0f / sum;
        const float zf  = qm ? 0.0f : 1.0f;
        float ent = 0.f;
        for (int s = q; s < ncs; s += 16) {
            float p = (inv != 0.0f) ? (__expf(sm.sS[r][s] - m) * inv * zf) : 0.0f;
            sm.sS[r][s] = p;
            ent -= p * __logf(fmaxf(p, EPSF));
        }
        #pragma unroll
        for (int k = 8; k >= 1; k >>= 1)
            ent += __shfl_xor_sync(0xffffffffu, ent, k);
        if (q == 0)
            outE[((size_t)b * Hq + h) * Lq + l0 + r] = ent;
    }
    __syncthreads();

    // ================= Phase 3: write A =================
    for (int p = t; p < TL * (Sq / 4); p += NTHR) {
        const int r = p / (Sq / 4);
        const int c = p % (Sq / 4);
        float4 v;
        if (4 * c < ncs) v = *reinterpret_cast<const float4*>(&sm.sS[r][4 * c]);
        else             v = make_float4(0.f, 0.f, 0.f, 0.f);
        *reinterpret_cast<float4*>(
            &outA[(((size_t)b * Hq + h) * Lq + l0 + r) * Sq + 4 * c]) = v;
    }

    // ================= Phase 4: V = att @ value =================
    const int half = t >> 7;        // split s range across thread halves
    const int tt   = t & 127;
    const int vrg  = tt >> 6;       // rows {8*vrg .. 8*vrg+7}
    const int ve   = tt & 63;
    float vacc[8];
    #pragma unroll
    for (int i = 0; i < 8; i++) vacc[i] = 0.f;

    for (int ch = 0; ch < nch; ch++) {
        const int c0 = ch * TS;
        __syncthreads();
        for (int p = t; p < TS * 16; p += NTHR) {
            int s = p >> 4, v = p & 15;
            const float4 kv = *reinterpret_cast<const float4*>(
                V + (((size_t)b * Sq + c0 + s) * Hq + h) * Eq + 4 * v);
            float* dst = &sm.sK[s][4 * v];
            dst[0] = kv.x; dst[1] = kv.y; dst[2] = kv.z; dst[3] = kv.w;
        }
        __syncthreads();
        const int sbase = 128 * half;
        for (int s4 = 0; s4 < 128; s4 += 4) {
            const int sl = sbase + s4;
            float vv0 = sm.sK[sl + 0][ve];
            float vv1 = sm.sK[sl + 1][ve];
            float vv2 = sm.sK[sl + 2][ve];
            float vv3 = sm.sK[sl + 3][ve];
            #pragma unroll
            for (int i = 0; i < 8; i++) {
                const float4 a4 = *reinterpret_cast<const float4*>(
                    &sm.sS[8 * vrg + i][c0 + sl]);
                vacc[i] += a4.x * vv0 + a4.y * vv1 + a4.z * vv2 + a4.w * vv3;
            }
        }
    }
    __syncthreads();
    if (half == 1) {
        #pragma unroll
        for (int i = 0; i < 8; i++) sm.sQ[8 * vrg + i][ve] = vacc[i];
    }
    __syncthreads();
    if (half == 0) {
        #pragma unroll
        for (int i = 0; i < 8; i++) {
            const int row = 8 * vrg + i;
            const float o = vacc[i] + sm.sQ[row][ve];
            outV[(((size_t)b * Lq + l0 + row) * Hq + h) * Eq + ve] = o;
        }
    }
}

extern "C" void kernel_launch(void* const* d_in, const int* in_sizes, int n_in,
                              void* d_out, int out_size) {
    const float* Q  = (const float*)d_in[0];
    const float* K  = (const float*)d_in[1];
    const float* V  = (const float*)d_in[2];
    const int* mk   = (const int*)d_in[3];
    const int* mq   = (const int*)d_in[4];
    const int* pos  = (const int*)d_in[5];
    const int* cm   = (const int*)d_in[6];
    float* out  = (float*)d_out;
    float* outV = out;
    float* outA = out + (size_t)Bq * Lq * Hq * Eq;
    float* outE = outA + (size_t)Bq * Hq * Lq * Sq;

    const size_t smem = sizeof(Smem);
    cudaFuncSetAttribute(attn_kernel,
                         cudaFuncAttributeMaxDynamicSharedMemorySize, (int)smem);
    attn_kernel<<<Bq * Hq * (Lq / TL), NTHR, smem>>>(Q, K, V, mk, mq, pos, cm,
                                                     outV, outA, outE);
}

// round 3
// speedup vs baseline: 1.2607x; 1.2607x over previous
#include <cuda_runtime.h>
#include <math.h>

#define Bq 2
#define Lq 2048
#define Sq 2048
#define Hq 8
#define Eq 64
#define TL 16          // l rows per block
#define TS 256         // s chunk
#define NTHR 256
#define SCALE 0.125f   // 1/sqrt(64)
#define EPSF 1e-8f

struct Smem {
    float sS[TL][Sq];       // scores -> att (131072 B)
    float sK[TS * Eq];      // K or V chunk, XOR-swizzled (65536 B)
    float sQ[TL][Eq];       // Q tile (4096 B)
    float sKm[Sq];          // 0 or -inf per key pos (8192 B)   } aliased as
    int   sPos[Sq];         // pos per key index (8192 B)       } sRed in phase 4
    int   sPl[TL];
    int   sQm[TL];
};

// float4 slot accessor with XOR swizzle: row stride 64 floats, slot ^ (row>>2)&15
__device__ __forceinline__ float4* kslot(float* base, int row, int slot) {
    return reinterpret_cast<float4*>(base + row * Eq + (((slot) ^ ((row >> 2) & 15)) << 2));
}

__global__ __launch_bounds__(NTHR, 1)
void attn_kernel(const float* __restrict__ Q, const float* __restrict__ K,
                 const float* __restrict__ V,
                 const int* __restrict__ mk, const int* __restrict__ mq,
                 const int* __restrict__ pos, const int* __restrict__ cmaskp,
                 float* __restrict__ outV, float* __restrict__ outA,
                 float* __restrict__ outE)
{
    extern __shared__ char smem_raw[];
    Smem& sm = *reinterpret_cast<Smem*>(smem_raw);
    const int t = threadIdx.x;
    const int TILES = Lq / TL;
    const int lt = blockIdx.x % TILES;
    const int h  = (blockIdx.x / TILES) % Hq;
    const int b  = blockIdx.x / (TILES * Hq);
    const int l0 = lt * TL;
    const int causal = cmaskp[0];

    // ---- preload masks / pos ----
    for (int s = t; s < Sq; s += NTHR) {
        sm.sKm[s]  = mk[b * Sq + s] ? -INFINITY : 0.0f;
        sm.sPos[s] = pos[b * Lq + s];
    }
    if (t < TL) {
        sm.sPl[t] = pos[b * Lq + l0 + t];
        sm.sQm[t] = mq[b * Lq + l0 + t];
    }
    // ---- load Q tile (16 rows x 64) ----
    {
        int r = t >> 4, v = t & 15;   // 256 threads -> 16x16 float4
        const float4 qv = *reinterpret_cast<const float4*>(
            Q + (((size_t)b * Lq + l0 + r) * Hq + h) * Eq + 4 * v);
        *reinterpret_cast<float4*>(&sm.sQ[r][4 * v]) = qv;
    }

    const int lmax = l0 + TL - 1;
    const int nch  = causal ? (lmax / TS + 1) : (Sq / TS);
    const int ncs  = nch * TS;

    // ================= Phase 1: scores (4x4 register tile) =================
    const int cg = t & 63;          // 64 col groups of 4
    const int rg = t >> 6;          // 4 row groups of 4
    for (int ch = 0; ch < nch; ch++) {
        const int c0 = ch * TS;
        __syncthreads();
        // load K chunk (coalesced) into swizzled SMEM
        for (int p = t; p < TS * 16; p += NTHR) {
            int s = p >> 4, v = p & 15;
            const float4 kv = *reinterpret_cast<const float4*>(
                K + (((size_t)b * Sq + c0 + s) * Hq + h) * Eq + 4 * v);
            *kslot(sm.sK, s, v) = kv;
        }
        __syncthreads();

        float acc[4][4];
        #pragma unroll
        for (int i = 0; i < 4; i++)
            #pragma unroll
            for (int j = 0; j < 4; j++) acc[i][j] = 0.f;

        #pragma unroll 2
        for (int e = 0; e < Eq; e += 4) {
            float4 qv[4], kv[4];
            #pragma unroll
            for (int i = 0; i < 4; i++)
                qv[i] = *reinterpret_cast<const float4*>(&sm.sQ[4 * rg + i][e]);
            #pragma unroll
            for (int j = 0; j < 4; j++)
                kv[j] = *kslot(sm.sK, 4 * cg + j, e >> 2);
            #pragma unroll
            for (int i = 0; i < 4; i++) {
                #pragma unroll
                for (int j = 0; j < 4; j++) {
                    acc[i][j] += qv[i].x * kv[j].x + qv[i].y * kv[j].y
                               + qv[i].z * kv[j].z + qv[i].w * kv[j].w;
                }
            }
        }

        const float4 km4 = *reinterpret_cast<const float4*>(&sm.sKm[c0 + 4 * cg]);
        const int4  ps4 = *reinterpret_cast<const int4*>(&sm.sPos[c0 + 4 * cg]);
        #pragma unroll
        for (int i = 0; i < 4; i++) {
            const int pl = sm.sPl[4 * rg + i];
            float4 o;
            o.x = acc[i][0] * SCALE + km4.x;
            o.y = acc[i][1] * SCALE + km4.y;
            o.z = acc[i][2] * SCALE + km4.z;
            o.w = acc[i][3] * SCALE + km4.w;
            if (causal) {
                if (ps4.x > pl) o.x = -INFINITY;
                if (ps4.y > pl) o.y = -INFINITY;
                if (ps4.z > pl) o.z = -INFINITY;
                if (ps4.w > pl) o.w = -INFINITY;
            }
            *reinterpret_cast<float4*>(&sm.sS[4 * rg + i][c0 + 4 * cg]) = o;
        }
    }
    __syncthreads();

    // ========== Phase 2: softmax + entropy (no max pass; scores bounded) ==========
    {
        const int r = t >> 4, q = t & 15;   // 16 threads per row
        const int qm = sm.sQm[r];
        float sum = 0.f;
        for (int s = q; s < ncs; s += 16) {
            const float e = __expf(sm.sS[r][s]);
            sm.sS[r][s] = e;
            sum += e;
        }
        #pragma unroll
        for (int k = 8; k >= 1; k >>= 1)
            sum += __shfl_xor_sync(0xffffffffu, sum, k);
        const float inv = (qm ? 0.0f : 1.0f) / sum;
        float ent = 0.f;
        for (int s = q; s < ncs; s += 16) {
            const float p = sm.sS[r][s] * inv;
            sm.sS[r][s] = p;
            ent -= p * __logf(fmaxf(p, EPSF));
        }
        #pragma unroll
        for (int k = 8; k >= 1; k >>= 1)
            ent += __shfl_xor_sync(0xffffffffu, ent, k);
        if (q == 0)
            outE[((size_t)b * Hq + h) * Lq + l0 + r] = ent;
    }
    __syncthreads();

    // ================= Phase 3: write A =================
    for (int p = t; p < TL * (Sq / 4); p += NTHR) {
        const int r = p / (Sq / 4);
        const int c = p % (Sq / 4);
        float4 v;
        if (4 * c < ncs) v = *reinterpret_cast<const float4*>(&sm.sS[r][4 * c]);
        else             v = make_float4(0.f, 0.f, 0.f, 0.f);
        *reinterpret_cast<float4*>(
            &outA[(((size_t)b * Hq + h) * Lq + l0 + r) * Sq + 4 * c]) = v;
    }

    // ====== Phase 4: V = att @ value (4-way s-split, 4x4 register tiles) ======
    const int sg  = t >> 6;        // s quarter within each chunk
    const int tt  = t & 63;
    const int rg4 = tt >> 4;       // rows {4*rg4 .. 4*rg4+3}
    const int eg  = tt & 15;       // e cols {4*eg .. 4*eg+3}
    float facc[4][4];
    #pragma unroll
    for (int i = 0; i < 4; i++)
        #pragma unroll
        for (int j = 0; j < 4; j++) facc[i][j] = 0.f;

    for (int ch = 0; ch < nch; ch++) {
        const int c0 = ch * TS;
        __syncthreads();
        for (int p = t; p < TS * 16; p += NTHR) {
            int s = p >> 4, v = p & 15;
            const float4 kv = *reinterpret_cast<const float4*>(
                V + (((size_t)b * Sq + c0 + s) * Hq + h) * Eq + 4 * v);
            *kslot(sm.sK, s, v) = kv;
        }
        __syncthreads();
        const int sl0 = 64 * sg;
        #pragma unroll 2
        for (int s4 = 0; s4 < 64; s4 += 4) {
            float a4[4][4], vv[4][4];
            #pragma unroll
            for (int i = 0; i < 4; i++) {
                const float4 av = *reinterpret_cast<const float4*>(
                    &sm.sS[4 * rg4 + i][c0 + sl0 + s4]);
                a4[i][0] = av.x; a4[i][1] = av.y; a4[i][2] = av.z; a4[i][3] = av.w;
            }
            #pragma unroll
            for (int k = 0; k < 4; k++) {
                const float4 vf = *kslot(sm.sK, sl0 + s4 + k, eg);
                vv[k][0] = vf.x; vv[k][1] = vf.y; vv[k][2] = vf.z; vv[k][3] = vf.w;
            }
            #pragma unroll
            for (int i = 0; i < 4; i++) {
                #pragma unroll
                for (int j = 0; j < 4; j++) {
                    facc[i][j] += a4[i][0] * vv[0][j] + a4[i][1] * vv[1][j]
                                + a4[i][2] * vv[2][j] + a4[i][3] * vv[3][j];
                }
            }
        }
    }
    __syncthreads();
    // reduce the 4 s-splits: groups 1..3 dump partials, group 0 accumulates
    float* sRed = reinterpret_cast<float*>(&sm.sKm[0]);   // 16KB region, free now
    if (sg > 0) {
        #pragma unroll
        for (int i = 0; i < 4; i++) {
            float4 w = make_float4(facc[i][0], facc[i][1], facc[i][2], facc[i][3]);
            *reinterpret_cast<float4*>(
                &sRed[(((sg - 1) * TL) + 4 * rg4 + i) * Eq + 4 * eg]) = w;
        }
    }
    __syncthreads();
    if (sg == 0) {
        #pragma unroll
        for (int i = 0; i < 4; i++) {
            const int row = 4 * rg4 + i;
            float4 o = make_float4(facc[i][0], facc[i][1], facc[i][2], facc[i][3]);
            #pragma unroll
            for (int l = 0; l < 3; l++) {
                const float4 w = *reinterpret_cast<const float4*>(
                    &sRed[((l * TL) + row) * Eq + 4 * eg]);
                o.x += w.x; o.y += w.y; o.z += w.z; o.w += w.w;
            }
            *reinterpret_cast<float4*>(
                &outV[(((size_t)b * Lq + l0 + row) * Hq + h) * Eq + 4 * eg]) = o;
        }
    }
}

extern "C" void kernel_launch(void* const* d_in, const int* in_sizes, int n_in,
                              void* d_out, int out_size) {
    const float* Q  = (const float*)d_in[0];
    const float* K  = (const float*)d_in[1];
    const float* V  = (const float*)d_in[2];
    const int* mk   = (const int*)d_in[3];
    const int* mq   = (const int*)d_in[4];
    const int* pos  = (const int*)d_in[5];
    const int* cm   = (const int*)d_in[6];
    float* out  = (float*)d_out;
    float* outV = out;
    float* outA = out + (size_t)Bq * Lq * Hq * Eq;
    float* outE = outA + (size_t)Bq * Hq * Lq * Sq;

    const size_t smem = sizeof(Smem);
    cudaFuncSetAttribute(attn_kernel,
                         cudaFuncAttributeMaxDynamicSharedMemorySize, (int)smem);
    attn_kernel<<<Bq * Hq * (Lq / TL), NTHR, smem>>>(Q, K, V, mk, mq, pos, cm,
                                                     outV, outA, outE);
}

// round 5
// speedup vs baseline: 2.2649x; 1.7966x over previous
#include <cuda_runtime.h>
#include <cuda_bf16.h>
#include <math.h>
#include <stdint.h>

#define Bq 2
#define Lq 2048
#define Sq 2048
#define Hq 8
#define Eq 64
#define TL 16
#define TS 128
#define NTHR 256
#define SCALE 0.125f

#define SSTR 2052      // sS row stride (f32)
#define KSTR 72        // K/V smem row stride (bf16)
#define ASTR 136       // sA row stride (bf16)

#define OFF_SS    0
#define OFF_KHI   131328
#define OFF_KLO   (OFF_KHI + 18432)
#define OFF_QHI   (OFF_KLO + 18432)
#define OFF_QLO   (OFF_QHI + 2304)
#define OFF_AHI   (OFF_QLO + 2304)
#define OFF_ALO   (OFF_AHI + 4352)
#define OFF_POSM  (OFF_ALO + 4352)
#define OFF_PL    (OFF_POSM + 8192)
#define OFF_QM    (OFF_PL + 64)
#define OFF_INV   (OFF_QM + 64)
#define OFF_RED   OFF_KHI          // 32KB reduction buffer aliases K area
#define SMEM_TOTAL (OFF_INV + 64)  // 189888 B

__device__ __forceinline__ uint32_t smem_u32(const void* p) {
    uint32_t a;
    asm("{ .reg .u64 t; cvta.to.shared.u64 t, %1; cvt.u32.u64 %0, t; }" : "=r"(a) : "l"(p));
    return a;
}
__device__ __forceinline__ void ldsm4(uint32_t a, uint32_t r[4]) {
    asm volatile("ldmatrix.sync.aligned.m8n8.x4.shared.b16 {%0,%1,%2,%3}, [%4];"
        : "=r"(r[0]), "=r"(r[1]), "=r"(r[2]), "=r"(r[3]) : "r"(a));
}
__device__ __forceinline__ void ldsm2(uint32_t a, uint32_t r[2]) {
    asm volatile("ldmatrix.sync.aligned.m8n8.x2.shared.b16 {%0,%1}, [%2];"
        : "=r"(r[0]), "=r"(r[1]) : "r"(a));
}
__device__ __forceinline__ void ldsm2t(uint32_t a, uint32_t r[2]) {
    asm volatile("ldmatrix.sync.aligned.m8n8.x2.trans.shared.b16 {%0,%1}, [%2];"
        : "=r"(r[0]), "=r"(r[1]) : "r"(a));
}
__device__ __forceinline__ void mma16816(float d[4], const uint32_t a[4], const uint32_t b[2]) {
    asm volatile("mma.sync.aligned.m16n8k16.row.col.f32.bf16.bf16.f32 "
        "{%0,%1,%2,%3}, {%4,%5,%6,%7}, {%8,%9}, {%0,%1,%2,%3};"
        : "+f"(d[0]), "+f"(d[1]), "+f"(d[2]), "+f"(d[3])
        : "r"(a[0]), "r"(a[1]), "r"(a[2]), "r"(a[3]), "r"(b[0]), "r"(b[1]));
}
__device__ __forceinline__ void cvt_hilo(float4 x, uint32_t& h01, uint32_t& h23,
                                         uint32_t& l01, uint32_t& l23) {
    __nv_bfloat162 a = __floats2bfloat162_rn(x.x, x.y);
    __nv_bfloat162 b = __floats2bfloat162_rn(x.z, x.w);
    float2 fa = __bfloat1622float2(a), fb = __bfloat1622float2(b);
    __nv_bfloat162 la = __floats2bfloat162_rn(x.x - fa.x, x.y - fa.y);
    __nv_bfloat162 lb = __floats2bfloat162_rn(x.z - fb.x, x.w - fb.y);
    h01 = *reinterpret_cast<uint32_t*>(&a);  h23 = *reinterpret_cast<uint32_t*>(&b);
    l01 = *reinterpret_cast<uint32_t*>(&la); l23 = *reinterpret_cast<uint32_t*>(&lb);
}

__global__ __launch_bounds__(NTHR, 1)
void attn_kernel(const float* __restrict__ Q, const float* __restrict__ K,
                 const float* __restrict__ V,
                 const int* __restrict__ mk, const int* __restrict__ mq,
                 const int* __restrict__ pos, const int* __restrict__ cmaskp,
                 float* __restrict__ outV, float* __restrict__ outA,
                 float* __restrict__ outE)
{
    extern __shared__ char smc[];
    const uint32_t smb = smem_u32(smc);
    const int t = threadIdx.x, warp = t >> 5, lane = t & 31;
    const int causal = cmaskp[0];

    // heavy-tiles-first schedule
    const int idx = blockIdx.x;
    const int lt  = 15 - (idx >> 7);
    const int sub = idx & 127;
    const int bh  = sub >> 3, li = sub & 7;
    const int b = bh >> 3, h = bh & 7;
    const int l0 = lt * 128 + li * TL;
    const int nch = causal ? (lt + 1) : (Sq / TS);
    const int ncs = nch * TS;

    float* sS   = (float*)(smc + OFF_SS);
    int*   posm = (int*)(smc + OFF_POSM);
    int*   sPl  = (int*)(smc + OFF_PL);
    int*   sQm  = (int*)(smc + OFF_QM);
    float* sInv = (float*)(smc + OFF_INV);

    // ---- prologue: masks/pos + Q hi/lo ----
    for (int s = t; s < Sq; s += NTHR) {
        const int m = mk[b * Sq + s];
        const int p = pos[b * Lq + s];
        posm[s] = m ? 0x7FFFFFFF : (causal ? p : (int)0x80000000);
    }
    if (t < TL) {
        sPl[t] = pos[b * Lq + l0 + t];
        sQm[t] = mq[b * Lq + l0 + t];
    }
    {
        const int r = t >> 4, v = t & 15;
        const float4 x = *reinterpret_cast<const float4*>(
            Q + (((size_t)b * Lq + l0 + r) * Hq + h) * Eq + 4 * v);
        uint32_t h01, h23, l01, l23; cvt_hilo(x, h01, h23, l01, l23);
        uint32_t* hp = (uint32_t*)(smc + OFF_QHI + r * 144 + v * 8);
        uint32_t* lp = (uint32_t*)(smc + OFF_QLO + r * 144 + v * 8);
        hp[0] = h01; hp[1] = h23; lp[0] = l01; lp[1] = l23;
    }
    __syncthreads();

    // ================= Phase 1: scores via mma =================
    uint32_t aq[2][4][4];
    {
        const int row = lane & 15, coff = (lane >> 4) * 8;
        #pragma unroll
        for (int kk = 0; kk < 4; kk++) {
            ldsm4(smb + OFF_QHI + row * 144 + (kk * 16 + coff) * 2, aq[0][kk]);
            ldsm4(smb + OFF_QLO + row * 144 + (kk * 16 + coff) * 2, aq[1][kk]);
        }
    }
    const int pl_lo = sPl[lane >> 2], pl_hi = sPl[8 + (lane >> 2)];

    for (int ch = 0; ch < nch; ch++) {
        const int c0 = ch * TS;
        __syncthreads();
        #pragma unroll
        for (int i = 0; i < 8; i++) {
            const int p = t + i * NTHR, s = p >> 4, v = p & 15;
            const float4 x = *reinterpret_cast<const float4*>(
                K + (((size_t)b * Sq + c0 + s) * Hq + h) * Eq + 4 * v);
            uint32_t h01, h23, l01, l23; cvt_hilo(x, h01, h23, l01, l23);
            uint32_t* hp = (uint32_t*)(smc + OFF_KHI + s * 144 + v * 8);
            uint32_t* lp = (uint32_t*)(smc + OFF_KLO + s * 144 + v * 8);
            hp[0] = h01; hp[1] = h23; lp[0] = l01; lp[1] = l23;
        }
        __syncthreads();
        #pragma unroll
        for (int nt = 0; nt < 2; nt++) {
            const int s0 = warp * 16 + nt * 8;
            float d[4] = {0.f, 0.f, 0.f, 0.f};
            const uint32_t brow = (uint32_t)(s0 + (lane & 7)) * 144;
            #pragma unroll
            for (int kk = 0; kk < 4; kk++) {
                uint32_t bh2[2], bl2[2];
                const uint32_t bco = (uint32_t)(kk * 16 + ((lane >> 3) & 1) * 8) * 2;
                ldsm2(smb + OFF_KHI + brow + bco, bh2);
                ldsm2(smb + OFF_KLO + brow + bco, bl2);
                mma16816(d, aq[0][kk], bh2);
                mma16816(d, aq[0][kk], bl2);
                mma16816(d, aq[1][kk], bh2);
            }
            const int c = c0 + s0 + (lane & 3) * 2;
            const int pm0 = posm[c], pm1 = posm[c + 1];
            float2 v0, v1;
            v0.x = (pm0 > pl_lo) ? -INFINITY : d[0] * SCALE;
            v0.y = (pm1 > pl_lo) ? -INFINITY : d[1] * SCALE;
            v1.x = (pm0 > pl_hi) ? -INFINITY : d[2] * SCALE;
            v1.y = (pm1 > pl_hi) ? -INFINITY : d[3] * SCALE;
            *reinterpret_cast<float2*>(&sS[(lane >> 2) * SSTR + c])       = v0;
            *reinterpret_cast<float2*>(&sS[((lane >> 2) + 8) * SSTR + c]) = v1;
        }
    }
    __syncthreads();

    // ===== Phase 2: exp + sum + entropy identity (no max, no log pass) =====
    {
        const int r = t >> 4, q = t & 15;
        float sum = 0.f, dot = 0.f;
        for (int col = q; col < ncs; col += 16) {
            const float v = sS[r * SSTR + col];
            const float e = __expf(v);
            sS[r * SSTR + col] = e;
            if (v > -1e30f) { sum += e; dot += e * v; }
        }
        #pragma unroll
        for (int k = 8; k >= 1; k >>= 1) {
            sum += __shfl_xor_sync(0xffffffffu, sum, k);
            dot += __shfl_xor_sync(0xffffffffu, dot, k);
        }
        if (q == 0) {
            const float zf = sQm[r] ? 0.f : 1.f;
            sInv[r] = zf / sum;
            outE[((size_t)b * Hq + h) * Lq + l0 + r] = zf * (__logf(sum) - dot / sum);
        }
    }
    __syncthreads();

    // ================= Phase 3: write A =================
    for (int p = t; p < TL * (Sq / 4); p += NTHR) {
        const int r = p >> 9;
        const int c4 = (p & 511) * 4;
        float4 v;
        if (c4 < ncs) {
            v = *reinterpret_cast<const float4*>(&sS[r * SSTR + c4]);
            const float inv = sInv[r];
            v.x *= inv; v.y *= inv; v.z *= inv; v.w *= inv;
        } else {
            v = make_float4(0.f, 0.f, 0.f, 0.f);
        }
        *reinterpret_cast<float4*>(
            &outA[(((size_t)b * Hq + h) * Lq + l0 + r) * Sq + c4]) = v;
    }

    // ================= Phase 4: O = exp(S) @ V via mma =================
    float o[8][4];
    #pragma unroll
    for (int nt = 0; nt < 8; nt++)
        #pragma unroll
        for (int j = 0; j < 4; j++) o[nt][j] = 0.f;

    for (int ch = 0; ch < nch; ch++) {
        const int c0 = ch * TS;
        __syncthreads();
        // build A chunk hi/lo bf16
        {
            const int r = t >> 4, v = t & 15;
            const float4 x0 = *reinterpret_cast<const float4*>(&sS[r * SSTR + c0 + 8 * v]);
            const float4 x1 = *reinterpret_cast<const float4*>(&sS[r * SSTR + c0 + 8 * v + 4]);
            uint32_t h01, h23, l01, l23;
            cvt_hilo(x0, h01, h23, l01, l23);
            uint32_t* hp = (uint32_t*)(smc + OFF_AHI + r * 272 + v * 16);
            uint32_t* lp = (uint32_t*)(smc + OFF_ALO + r * 272 + v * 16);
            hp[0] = h01; hp[1] = h23; lp[0] = l01; lp[1] = l23;
            cvt_hilo(x1, h01, h23, l01, l23);
            hp[2] = h01; hp[3] = h23; lp[2] = l01; lp[3] = l23;
        }
        // load V chunk hi/lo
        #pragma unroll
        for (int i = 0; i < 8; i++) {
            const int p = t + i * NTHR, s = p >> 4, v = p & 15;
            const float4 x = *reinterpret_cast<const float4*>(
                V + (((size_t)b * Sq + c0 + s) * Hq + h) * Eq + 4 * v);
            uint32_t h01, h23, l01, l23; cvt_hilo(x, h01, h23, l01, l23);
            uint32_t* hp = (uint32_t*)(smc + OFF_KHI + s * 144 + v * 8);
            uint32_t* lp = (uint32_t*)(smc + OFF_KLO + s * 144 + v * 8);
            hp[0] = h01; hp[1] = h23; lp[0] = l01; lp[1] = l23;
        }
        __syncthreads();
        // A fragments (k-range = warp*16 .. +15)
        uint32_t aa[2][4];
        {
            const int row = lane & 15, coff = warp * 16 + (lane >> 4) * 8;
            ldsm4(smb + OFF_AHI + row * 272 + coff * 2, aa[0]);
            ldsm4(smb + OFF_ALO + row * 272 + coff * 2, aa[1]);
        }
        const uint32_t vrow = (uint32_t)(warp * 16 + (lane & 7) + ((lane >> 3) & 1) * 8) * 144;
        #pragma unroll
        for (int nt = 0; nt < 8; nt++) {
            uint32_t bh2[2], bl2[2];
            ldsm2t(smb + OFF_KHI + vrow + nt * 16, bh2);
            ldsm2t(smb + OFF_KLO + vrow + nt * 16, bl2);
            mma16816(o[nt], aa[0], bh2);
            mma16816(o[nt], aa[0], bl2);
            mma16816(o[nt], aa[1], bh2);
        }
    }
    __syncthreads();
    // dump partials and reduce over 8 warps
    float* sRed = (float*)(smc + OFF_RED);   // [8][16][64]
    {
        const int r = lane >> 2, c = (lane & 3) * 2;
        #pragma unroll
        for (int nt = 0; nt < 8; nt++) {
            *reinterpret_cast<float2*>(&sRed[(warp * TL + r) * 64 + nt * 8 + c])       = make_float2(o[nt][0], o[nt][1]);
            *reinterpret_cast<float2*>(&sRed[(warp * TL + r + 8) * 64 + nt * 8 + c])   = make_float2(o[nt][2], o[nt][3]);
        }
    }
    __syncthreads();
    {
        const int r = t >> 4, c4 = (t & 15) * 4;
        float4 acc = make_float4(0.f, 0.f, 0.f, 0.f);
        #pragma unroll
        for (int w = 0; w < 8; w++) {
            const float4 x = *reinterpret_cast<const float4*>(&sRed[(w * TL + r) * 64 + c4]);
            acc.x += x.x; acc.y += x.y; acc.z += x.z; acc.w += x.w;
        }
        const float inv = sInv[r];
        acc.x *= inv; acc.y *= inv; acc.z *= inv; acc.w *= inv;
        *reinterpret_cast<float4*>(
            &outV[(((size_t)b * Lq + l0 + r) * Hq + h) * Eq + c4]) = acc;
    }
}

extern "C" void kernel_launch(void* const* d_in, const int* in_sizes, int n_in,
                              void* d_out, int out_size) {
    const float* Q  = (const float*)d_in[0];
    const float* K  = (const float*)d_in[1];
    const float* V  = (const float*)d_in[2];
    const int* mk   = (const int*)d_in[3];
    const int* mq   = (const int*)d_in[4];
    const int* pos  = (const int*)d_in[5];
    const int* cm   = (const int*)d_in[6];
    float* out  = (float*)d_out;
    float* outV = out;
    float* outA = out + (size_t)Bq * Lq * Hq * Eq;
    float* outE = outA + (size_t)Bq * Hq * Lq * Sq;

    cudaFuncSetAttribute(attn_kernel,
                         cudaFuncAttributeMaxDynamicSharedMemorySize, SMEM_TOTAL);
    attn_kernel<<<Bq * Hq * (Lq / TL), NTHR, SMEM_TOTAL>>>(Q, K, V, mk, mq, pos, cm,
                                                           outV, outA, outE);
}

// round 6
// speedup vs baseline: 2.4876x; 1.0983x over previous
#include <cuda_runtime.h>
#include <cuda_bf16.h>
#include <math.h>
#include <stdint.h>

#define Bq 2
#define Lq 2048
#define Sq 2048
#define Hq 8
#define Eq 64
#define TL 16
#define TS 128
#define NTHR 256
#define SCALE 0.125f

#define SSTR 2052

#define OFF_SS    0
#define OFF_KHI   131328
#define OFF_KLO   (OFF_KHI + 18432)
#define OFF_VHI   (OFF_KLO + 18432)
#define OFF_VLO   (OFF_VHI + 18432)
#define OFF_QHI   (OFF_VLO + 18432)
#define OFF_QLO   (OFF_QHI + 2304)
#define OFF_POSM  (OFF_QLO + 2304)
#define OFF_PL    (OFF_POSM + 8192)
#define OFF_QM    (OFF_PL + 64)
#define OFF_INV   (OFF_QM + 64)
#define OFF_SUM   (OFF_INV + 64)
#define OFF_DOT   (OFF_SUM + 512)
#define OFF_RED   OFF_KHI            // 32KB O-reduction buffer aliases K tiles
#define SMEM_TOTAL (OFF_DOT + 512)   // 219072 B

__device__ __forceinline__ uint32_t smem_u32(const void* p) {
    uint32_t a;
    asm("{ .reg .u64 t; cvta.to.shared.u64 t, %1; cvt.u32.u64 %0, t; }" : "=r"(a) : "l"(p));
    return a;
}
__device__ __forceinline__ void ldsm4(uint32_t a, uint32_t r[4]) {
    asm volatile("ldmatrix.sync.aligned.m8n8.x4.shared.b16 {%0,%1,%2,%3}, [%4];"
        : "=r"(r[0]), "=r"(r[1]), "=r"(r[2]), "=r"(r[3]) : "r"(a));
}
__device__ __forceinline__ void ldsm2(uint32_t a, uint32_t r[2]) {
    asm volatile("ldmatrix.sync.aligned.m8n8.x2.shared.b16 {%0,%1}, [%2];"
        : "=r"(r[0]), "=r"(r[1]) : "r"(a));
}
__device__ __forceinline__ void ldsm2t(uint32_t a, uint32_t r[2]) {
    asm volatile("ldmatrix.sync.aligned.m8n8.x2.trans.shared.b16 {%0,%1}, [%2];"
        : "=r"(r[0]), "=r"(r[1]) : "r"(a));
}
__device__ __forceinline__ void mma16816(float d[4], const uint32_t a[4], const uint32_t b[2]) {
    asm volatile("mma.sync.aligned.m16n8k16.row.col.f32.bf16.bf16.f32 "
        "{%0,%1,%2,%3}, {%4,%5,%6,%7}, {%8,%9}, {%0,%1,%2,%3};"
        : "+f"(d[0]), "+f"(d[1]), "+f"(d[2]), "+f"(d[3])
        : "r"(a[0]), "r"(a[1]), "r"(a[2]), "r"(a[3]), "r"(b[0]), "r"(b[1]));
}
__device__ __forceinline__ void cvt_hilo(float4 x, uint32_t& h01, uint32_t& h23,
                                         uint32_t& l01, uint32_t& l23) {
    __nv_bfloat162 a = __floats2bfloat162_rn(x.x, x.y);
    __nv_bfloat162 b = __floats2bfloat162_rn(x.z, x.w);
    float2 fa = __bfloat1622float2(a), fb = __bfloat1622float2(b);
    __nv_bfloat162 la = __floats2bfloat162_rn(x.x - fa.x, x.y - fa.y);
    __nv_bfloat162 lb = __floats2bfloat162_rn(x.z - fb.x, x.w - fb.y);
    h01 = *reinterpret_cast<uint32_t*>(&a);  h23 = *reinterpret_cast<uint32_t*>(&b);
    l01 = *reinterpret_cast<uint32_t*>(&la); l23 = *reinterpret_cast<uint32_t*>(&lb);
}
__device__ __forceinline__ uint32_t pack_hi(float a, float b, uint32_t& lo) {
    __nv_bfloat162 h = __floats2bfloat162_rn(a, b);
    float2 hf = __bfloat1622float2(h);
    __nv_bfloat162 l = __floats2bfloat162_rn(a - hf.x, b - hf.y);
    lo = *reinterpret_cast<uint32_t*>(&l);
    return *reinterpret_cast<uint32_t*>(&h);
}
// fast exp on the FMA pipe: rint via magic constant, deg-5 exp2 poly, exponent splice
__device__ __forceinline__ float fexp(float x) {
    const float L2E = 1.4426950408889634f;
    float y = fmaf(x, L2E, 12582912.0f);          // magic: 1.5 * 2^23
    int   im = __float_as_int(y) << 23;           // n << 23
    float i  = y - 12582912.0f;                   // rint(x * log2e)
    float f  = fmaf(x, L2E, -i);                  // f in [-0.5, 0.5]
    float p  =        1.3333558146e-3f;
    p = fmaf(p, f,    9.6181291076e-3f);
    p = fmaf(p, f,    5.5504108664e-2f);
    p = fmaf(p, f,    2.4022650696e-1f);
    p = fmaf(p, f,    6.9314718056e-1f);
    p = fmaf(p, f,    1.0f);
    return p * __int_as_float(im + 0x3f800000);
}

__global__ __launch_bounds__(NTHR, 1)
void attn_kernel(const float* __restrict__ Q, const float* __restrict__ K,
                 const float* __restrict__ V,
                 const int* __restrict__ mk, const int* __restrict__ mq,
                 const int* __restrict__ pos, const int* __restrict__ cmaskp,
                 float* __restrict__ outV, float* __restrict__ outA,
                 float* __restrict__ outE)
{
    extern __shared__ char smc[];
    const uint32_t smb = smem_u32(smc);
    const int t = threadIdx.x, warp = t >> 5, lane = t & 31;
    const int causal = cmaskp[0];

    // heavy-tiles-first schedule
    const int idx = blockIdx.x;
    const int lt  = 15 - (idx >> 7);
    const int sub = idx & 127;
    const int bh  = sub >> 3, li = sub & 7;
    const int b = bh >> 3, h = bh & 7;
    const int l0 = lt * 128 + li * TL;
    const int nch = causal ? (lt + 1) : (Sq / TS);
    const int ncs = nch * TS;

    float* sS   = (float*)(smc + OFF_SS);
    int*   posm = (int*)(smc + OFF_POSM);
    int*   sPl  = (int*)(smc + OFF_PL);
    int*   sQm  = (int*)(smc + OFF_QM);
    float* sInv = (float*)(smc + OFF_INV);
    float* sSum = (float*)(smc + OFF_SUM);   // [16 rows][8 warps]
    float* sDot = (float*)(smc + OFF_DOT);

    // ---- prologue: masks/pos + Q hi/lo ----
    for (int s = t; s < Sq; s += NTHR) {
        const int m = mk[b * Sq + s];
        const int p = pos[b * Lq + s];
        posm[s] = m ? 0x7FFFFFFF : (causal ? p : (int)0x80000000);
    }
    if (t < TL) {
        sPl[t] = pos[b * Lq + l0 + t];
        sQm[t] = mq[b * Lq + l0 + t];
    }
    {
        const int r = t >> 4, v = t & 15;
        const float4 x = *reinterpret_cast<const float4*>(
            Q + (((size_t)b * Lq + l0 + r) * Hq + h) * Eq + 4 * v);
        uint32_t h01, h23, l01, l23; cvt_hilo(x, h01, h23, l01, l23);
        uint32_t* hp = (uint32_t*)(smc + OFF_QHI + r * 144 + v * 8);
        uint32_t* lp = (uint32_t*)(smc + OFF_QLO + r * 144 + v * 8);
        hp[0] = h01; hp[1] = h23; lp[0] = l01; lp[1] = l23;
    }
    __syncthreads();

    // Q fragments, persistent
    uint32_t aq[2][4][4];
    {
        const int row = lane & 15, coff = (lane >> 4) * 8;
        #pragma unroll
        for (int kk = 0; kk < 4; kk++) {
            ldsm4(smb + OFF_QHI + row * 144 + (kk * 16 + coff) * 2, aq[0][kk]);
            ldsm4(smb + OFF_QLO + row * 144 + (kk * 16 + coff) * 2, aq[1][kk]);
        }
    }
    const int pl_lo = sPl[lane >> 2], pl_hi = sPl[8 + (lane >> 2)];

    float o[8][4];
    #pragma unroll
    for (int nt = 0; nt < 8; nt++)
        #pragma unroll
        for (int j = 0; j < 4; j++) o[nt][j] = 0.f;
    float rs[2] = {0.f, 0.f}, rd[2] = {0.f, 0.f};

    // ================= fused chunk loop =================
    for (int ch = 0; ch < nch; ch++) {
        const int c0 = ch * TS;
        // ---- load K and V chunks -> hi/lo bf16 smem ----
        #pragma unroll
        for (int i = 0; i < 8; i++) {
            const int p = t + i * NTHR, s = p >> 4, v = p & 15;
            const float4 x = *reinterpret_cast<const float4*>(
                K + (((size_t)b * Sq + c0 + s) * Hq + h) * Eq + 4 * v);
            uint32_t h01, h23, l01, l23; cvt_hilo(x, h01, h23, l01, l23);
            uint32_t* hp = (uint32_t*)(smc + OFF_KHI + s * 144 + v * 8);
            uint32_t* lp = (uint32_t*)(smc + OFF_KLO + s * 144 + v * 8);
            hp[0] = h01; hp[1] = h23; lp[0] = l01; lp[1] = l23;
        }
        #pragma unroll
        for (int i = 0; i < 8; i++) {
            const int p = t + i * NTHR, s = p >> 4, v = p & 15;
            const float4 x = *reinterpret_cast<const float4*>(
                V + (((size_t)b * Sq + c0 + s) * Hq + h) * Eq + 4 * v);
            uint32_t h01, h23, l01, l23; cvt_hilo(x, h01, h23, l01, l23);
            uint32_t* hp = (uint32_t*)(smc + OFF_VHI + s * 144 + v * 8);
            uint32_t* lp = (uint32_t*)(smc + OFF_VLO + s * 144 + v * 8);
            hp[0] = h01; hp[1] = h23; lp[0] = l01; lp[1] = l23;
        }
        __syncthreads();

        // ---- QK^T + epilogue: A-fragments built in registers ----
        uint32_t ahi[4], alo[4];
        #pragma unroll
        for (int nt = 0; nt < 2; nt++) {
            const int s0 = warp * 16 + nt * 8;
            float d[4] = {0.f, 0.f, 0.f, 0.f};
            const uint32_t brow = (uint32_t)(s0 + (lane & 7)) * 144;
            #pragma unroll
            for (int kk = 0; kk < 4; kk++) {
                uint32_t bh2[2], bl2[2];
                const uint32_t bco = (uint32_t)(kk * 16 + ((lane >> 3) & 1) * 8) * 2;
                ldsm2(smb + OFF_KHI + brow + bco, bh2);
                ldsm2(smb + OFF_KLO + brow + bco, bl2);
                mma16816(d, aq[0][kk], bh2);
                mma16816(d, aq[0][kk], bl2);
                mma16816(d, aq[1][kk], bh2);
            }
            const int c = c0 + s0 + (lane & 3) * 2;
            const int pm0 = posm[c], pm1 = posm[c + 1];
            const float v0 = (pm0 > pl_lo) ? -60.f : d[0] * SCALE;
            const float v1 = (pm1 > pl_lo) ? -60.f : d[1] * SCALE;
            const float v2 = (pm0 > pl_hi) ? -60.f : d[2] * SCALE;
            const float v3 = (pm1 > pl_hi) ? -60.f : d[3] * SCALE;
            const float e0 = fexp(v0), e1 = fexp(v1), e2 = fexp(v2), e3 = fexp(v3);
            rs[0] += e0 + e1;           rs[1] += e2 + e3;
            rd[0] += e0 * v0 + e1 * v1; rd[1] += e2 * v2 + e3 * v3;
            *reinterpret_cast<float2*>(&sS[(lane >> 2) * SSTR + c])       = make_float2(e0, e1);
            *reinterpret_cast<float2*>(&sS[((lane >> 2) + 8) * SSTR + c]) = make_float2(e2, e3);
            ahi[nt * 2 + 0] = pack_hi(e0, e1, alo[nt * 2 + 0]);
            ahi[nt * 2 + 1] = pack_hi(e2, e3, alo[nt * 2 + 1]);
        }

        // ---- AV: O += exp(S)[:, warp's k-slice] @ V ----
        const uint32_t vrow = (uint32_t)(warp * 16 + (lane & 7) + ((lane >> 3) & 1) * 8) * 144;
        #pragma unroll
        for (int nt = 0; nt < 8; nt++) {
            uint32_t bh2[2], bl2[2];
            ldsm2t(smb + OFF_VHI + vrow + nt * 16, bh2);
            ldsm2t(smb + OFF_VLO + vrow + nt * 16, bl2);
            mma16816(o[nt], ahi, bh2);
            mma16816(o[nt], ahi, bl2);
            mma16816(o[nt], alo, bh2);
        }
        __syncthreads();
    }

    // ---- row sum/dot reduction ----
    #pragma unroll
    for (int k = 1; k <= 2; k <<= 1) {
        rs[0] += __shfl_xor_sync(0xffffffffu, rs[0], k);
        rs[1] += __shfl_xor_sync(0xffffffffu, rs[1], k);
        rd[0] += __shfl_xor_sync(0xffffffffu, rd[0], k);
        rd[1] += __shfl_xor_sync(0xffffffffu, rd[1], k);
    }
    if ((lane & 3) == 0) {
        const int r = lane >> 2;
        sSum[r * 8 + warp]       = rs[0];
        sSum[(r + 8) * 8 + warp] = rs[1];
        sDot[r * 8 + warp]       = rd[0];
        sDot[(r + 8) * 8 + warp] = rd[1];
    }
    // ---- dump O partials (aliases K smem; safe after last sync) ----
    float* sRed = (float*)(smc + OFF_RED);   // [8 warps][16 rows][64]
    {
        const int r = lane >> 2, c = (lane & 3) * 2;
        #pragma unroll
        for (int nt = 0; nt < 8; nt++) {
            *reinterpret_cast<float2*>(&sRed[(warp * TL + r) * 64 + nt * 8 + c])     = make_float2(o[nt][0], o[nt][1]);
            *reinterpret_cast<float2*>(&sRed[(warp * TL + r + 8) * 64 + nt * 8 + c]) = make_float2(o[nt][2], o[nt][3]);
        }
    }
    __syncthreads();
    if (t < TL) {
        float S = 0.f, Dd = 0.f;
        #pragma unroll
        for (int w = 0; w < 8; w++) { S += sSum[t * 8 + w]; Dd += sDot[t * 8 + w]; }
        const float zf = sQm[t] ? 0.f : 1.f;
        sInv[t] = zf / S;
        outE[((size_t)b * Hq + h) * Lq + l0 + t] = zf * (__logf(S) - Dd / S);
    }
    __syncthreads();

    // ---- write V output ----
    {
        const int r = t >> 4, c4 = (t & 15) * 4;
        float4 acc = make_float4(0.f, 0.f, 0.f, 0.f);
        #pragma unroll
        for (int w = 0; w < 8; w++) {
            const float4 x = *reinterpret_cast<const float4*>(&sRed[(w * TL + r) * 64 + c4]);
            acc.x += x.x; acc.y += x.y; acc.z += x.z; acc.w += x.w;
        }
        const float inv = sInv[r];
        acc.x *= inv; acc.y *= inv; acc.z *= inv; acc.w *= inv;
        *reinterpret_cast<float4*>(
            &outV[(((size_t)b * Lq + l0 + r) * Hq + h) * Eq + c4]) = acc;
    }

    // ---- write A (normalize + zero-fill) ----
    for (int p = t; p < TL * (Sq / 4); p += NTHR) {
        const int r = p >> 9;
        const int c4 = (p & 511) * 4;
        float4 v;
        if (c4 < ncs) {
            v = *reinterpret_cast<const float4*>(&sS[r * SSTR + c4]);
            const float inv = sInv[r];
            v.x *= inv; v.y *= inv; v.z *= inv; v.w *= inv;
        } else {
            v = make_float4(0.f, 0.f, 0.f, 0.f);
        }
        *reinterpret_cast<float4*>(
            &outA[(((size_t)b * Hq + h) * Lq + l0 + r) * Sq + c4]) = v;
    }
}

extern "C" void kernel_launch(void* const* d_in, const int* in_sizes, int n_in,
                              void* d_out, int out_size) {
    const float* Q  = (const float*)d_in[0];
    const float* K  = (const float*)d_in[1];
    const float* V  = (const float*)d_in[2];
    const int* mk   = (const int*)d_in[3];
    const int* mq   = (const int*)d_in[4];
    const int* pos  = (const int*)d_in[5];
    const int* cm   = (const int*)d_in[6];
    float* out  = (float*)d_out;
    float* outV = out;
    float* outA = out + (size_t)Bq * Lq * Hq * Eq;
    float* outE = outA + (size_t)Bq * Hq * Lq * Sq;

    cudaFuncSetAttribute(attn_kernel,
                         cudaFuncAttributeMaxDynamicSharedMemorySize, SMEM_TOTAL);
    attn_kernel<<<Bq * Hq * (Lq / TL), NTHR, SMEM_TOTAL>>>(Q, K, V, mk, mq, pos, cm,
                                                           outV, outA, outE);
}